// round 12
// baseline (speedup 1.0000x reference)
#include <cuda_runtime.h>
#include <cuda_bf16.h>
#include <cstdint>

// Problem dims (fixed)
#define BB 2
#define SS 2048
#define DD 1024
#define HH 16
#define DHH 64
#define MM (BB*SS)   // 4096

// Scratch (allocation-free rule: __device__ globals)
__device__ __nv_bfloat16 g_Qh[BB*SS*DD];
__device__ __nv_bfloat16 g_Ql[BB*SS*DD];
__device__ __nv_bfloat16 g_Kh[BB*SS*DD];
__device__ __nv_bfloat16 g_Kl[BB*SS*DD];
__device__ __nv_bfloat16 g_Vth[BB*SS*DD];   // [bh][d][key]
__device__ __nv_bfloat16 g_Vtl[BB*SS*DD];
__device__ float g_O[BB*SS*DD];

// ---------------------------------------------------------------------------
// helpers
// ---------------------------------------------------------------------------
__device__ __forceinline__ unsigned f2tf(float f) {
    unsigned u;
    asm("cvt.rna.tf32.f32 %0, %1;" : "=r"(u) : "f"(f));
    return u;
}

__device__ __forceinline__ void mma_tf32(float* c, const unsigned* a, const unsigned* b) {
    asm volatile(
        "mma.sync.aligned.m16n8k8.row.col.f32.tf32.tf32.f32 "
        "{%0,%1,%2,%3}, {%4,%5,%6,%7}, {%8,%9}, {%0,%1,%2,%3};"
        : "+f"(c[0]), "+f"(c[1]), "+f"(c[2]), "+f"(c[3])
        : "r"(a[0]), "r"(a[1]), "r"(a[2]), "r"(a[3]),
          "r"(b[0]), "r"(b[1]));
}

__device__ __forceinline__ void mma_bf16(float* c, const unsigned* a, const unsigned* b) {
    asm volatile(
        "mma.sync.aligned.m16n8k16.row.col.f32.bf16.bf16.f32 "
        "{%0,%1,%2,%3}, {%4,%5,%6,%7}, {%8,%9}, {%0,%1,%2,%3};"
        : "+f"(c[0]), "+f"(c[1]), "+f"(c[2]), "+f"(c[3])
        : "r"(a[0]), "r"(a[1]), "r"(a[2]), "r"(a[3]),
          "r"(b[0]), "r"(b[1]));
}

__device__ __forceinline__ void mma_bf16_k8(float* c, const unsigned* a, unsigned b) {
    asm volatile(
        "mma.sync.aligned.m16n8k8.row.col.f32.bf16.bf16.f32 "
        "{%0,%1,%2,%3}, {%4,%5}, {%6}, {%0,%1,%2,%3};"
        : "+f"(c[0]), "+f"(c[1]), "+f"(c[2]), "+f"(c[3])
        : "r"(a[0]), "r"(a[1]), "r"(b));
}

__device__ __forceinline__ void split2f(float2 v, unsigned& hi, unsigned& lo) {
    __nv_bfloat162 h, l;
    h.x = __float2bfloat16_rn(v.x);
    h.y = __float2bfloat16_rn(v.y);
    l.x = __float2bfloat16_rn(v.x - __bfloat162float(h.x));
    l.y = __float2bfloat16_rn(v.y - __bfloat162float(h.y));
    hi = *(unsigned*)&h;
    lo = *(unsigned*)&l;
}

__device__ __forceinline__ void cpasync16(void* dst, const void* src) {
    unsigned d = (unsigned)__cvta_generic_to_shared(dst);
    asm volatile("cp.async.cg.shared.global [%0], [%1], 16;" :: "r"(d), "l"(src));
}
__device__ __forceinline__ void cp_commit() {
    asm volatile("cp.async.commit_group;");
}
template<int N> __device__ __forceinline__ void cp_wait() {
    asm volatile("cp.async.wait_group %0;" :: "n"(N));
}

__device__ __forceinline__ void ldmx4(unsigned& r0, unsigned& r1, unsigned& r2, unsigned& r3,
                                      const void* p) {
    unsigned a = (unsigned)__cvta_generic_to_shared(p);
    asm volatile("ldmatrix.sync.aligned.m8n8.x4.shared.b16 {%0,%1,%2,%3}, [%4];"
                 : "=r"(r0), "=r"(r1), "=r"(r2), "=r"(r3) : "r"(a));
}

// ---------------------------------------------------------------------------
// Tensor-core GEMM: C = X @ W^T (tf32, fp32 accum). CTA tile 128x64, 8 warps.
// MODE 0: split-bf16 output, head layout [bh][s][dh]  (Q, K)
// MODE 3: split-bf16 output, transposed [bh][dh][s]   (V)
// MODE 1: fp32 row-major [M,N]                        (final)
// ---------------------------------------------------------------------------
template<int MODE>
__global__ void __launch_bounds__(256, 2)
gemm_tc(const float* __restrict__ X, const float* __restrict__ W,
        __nv_bfloat16* __restrict__ Chi, __nv_bfloat16* __restrict__ Clo,
        float* __restrict__ C32)
{
    __shared__ __align__(16) float Xs[128][36];
    __shared__ __align__(16) float Ws[64][36];

    int tid  = threadIdx.x;
    int lane = tid & 31;
    int wid  = tid >> 5;
    int wm = wid >> 1;
    int wn = wid & 1;
    int g  = lane >> 2;
    int tg = lane & 3;
    int row0 = blockIdx.y * 128;
    int col0 = blockIdx.x * 64;

    float acc[2][4][4];
    #pragma unroll
    for (int h = 0; h < 2; ++h)
        #pragma unroll
        for (int j = 0; j < 4; ++j)
            #pragma unroll
            for (int e = 0; e < 4; ++e) acc[h][j][e] = 0.f;

    for (int k0 = 0; k0 < DD; k0 += 32) {
        #pragma unroll
        for (int it = 0; it < 4; ++it) {
            int idx = tid + it * 256;
            int r  = idx >> 3;
            int c4 = (idx & 7) << 2;
            *(float4*)&Xs[r][c4] = *(const float4*)&X[(size_t)(row0 + r) * DD + k0 + c4];
        }
        #pragma unroll
        for (int it = 0; it < 2; ++it) {
            int idx = tid + it * 256;
            int r  = idx >> 3;
            int c4 = (idx & 7) << 2;
            *(float4*)&Ws[r][c4] = *(const float4*)&W[(size_t)(col0 + r) * DD + k0 + c4];
        }
        __syncthreads();

        #pragma unroll
        for (int k8 = 0; k8 < 4; ++k8) {
            int kk = k8 * 8;
            unsigned a[2][4], b[4][2];
            #pragma unroll
            for (int h = 0; h < 2; ++h) {
                int r = wm * 32 + h * 16 + g;
                a[h][0] = f2tf(Xs[r][kk + tg]);
                a[h][1] = f2tf(Xs[r + 8][kk + tg]);
                a[h][2] = f2tf(Xs[r][kk + tg + 4]);
                a[h][3] = f2tf(Xs[r + 8][kk + tg + 4]);
            }
            #pragma unroll
            for (int j = 0; j < 4; ++j) {
                int n = wn * 32 + j * 8 + g;
                b[j][0] = f2tf(Ws[n][kk + tg]);
                b[j][1] = f2tf(Ws[n][kk + tg + 4]);
            }
            #pragma unroll
            for (int h = 0; h < 2; ++h)
                #pragma unroll
                for (int j = 0; j < 4; ++j)
                    mma_tf32(acc[h][j], a[h], b[j]);
        }
        __syncthreads();
    }

    #pragma unroll
    for (int h = 0; h < 2; ++h) {
        #pragma unroll
        for (int j = 0; j < 4; ++j) {
            int m0 = row0 + wm * 32 + h * 16 + g;
            int n0 = col0 + wn * 32 + j * 8 + 2 * tg;
            #pragma unroll
            for (int half = 0; half < 2; ++half) {
                int m = m0 + half * 8;
                float vx = acc[h][j][half * 2 + 0];
                float vy = acc[h][j][half * 2 + 1];
                if (MODE == 1) {
                    float2 val; val.x = vx; val.y = vy;
                    *(float2*)&C32[(size_t)m * DD + n0] = val;
                } else if (MODE == 0) {
                    int b_ = m >> 11, s_ = m & 2047;
                    int h_ = n0 >> 6, d_ = n0 & 63;
                    size_t base = ((size_t)(((b_ << 4) + h_) * SS + s_)) * DHH + d_;
                    __nv_bfloat162 hv, lv;
                    hv.x = __float2bfloat16_rn(vx);
                    hv.y = __float2bfloat16_rn(vy);
                    lv.x = __float2bfloat16_rn(vx - __bfloat162float(hv.x));
                    lv.y = __float2bfloat16_rn(vy - __bfloat162float(hv.y));
                    *(__nv_bfloat162*)&Chi[base] = hv;
                    *(__nv_bfloat162*)&Clo[base] = lv;
                } else {           // MODE 3: transposed V
                    int b_ = m >> 11, s_ = m & 2047;
                    #pragma unroll
                    for (int e = 0; e < 2; ++e) {
                        int d = n0 + e;
                        int h_ = d >> 6, dd = d & 63;
                        size_t base = ((size_t)(((b_ << 4) + h_) * DHH + dd)) * SS + s_;
                        float v = e ? vy : vx;
                        __nv_bfloat16 hb = __float2bfloat16_rn(v);
                        Chi[base] = hb;
                        Clo[base] = __float2bfloat16_rn(v - __bfloat162float(hb));
                    }
                }
            }
        }
    }
}

// ---------------------------------------------------------------------------
// Fused attention: warp-private K/V pipelines, register-resident P.
// CTA = 16 q rows of one (b,h), 512 threads. Warp w owns keys {t*128+w*8}.
// Phase 1: Q@K^T via m16n8k16 (3-term split), scores -> 64 regs/thread.
// Phase 2: register softmax, two tiny smem reduces, attn write from regs.
// Phase 3: P@V via m16n8k8 (A = packed P regs), per-warp partials, reduce.
// ---------------------------------------------------------------------------
#define KW_STRIDE 4608
#define KBUF 2304
#define KPART 1152
#define VBASE 73728
#define VW_STRIDE 4096
#define VBUF 2048
#define VPART 1024
#define QBASE 139264
#define QLOB  (QBASE + 2304)
#define REDB  143872
#define SMEM_ATTN 145920

__global__ void __launch_bounds__(512, 1)
attn_kernel(const int* __restrict__ mask, float* __restrict__ attn_out,
            int write_attn,
            const __nv_bfloat16* __restrict__ Qh, const __nv_bfloat16* __restrict__ Ql,
            const __nv_bfloat16* __restrict__ Kh, const __nv_bfloat16* __restrict__ Kl,
            const __nv_bfloat16* __restrict__ Vth, const __nv_bfloat16* __restrict__ Vtl,
            float* __restrict__ O)
{
    extern __shared__ char sm[];
    float* red     = (float*)(sm + REDB);
    float* partial = (float*)sm;

    int tid  = threadIdx.x;
    int lane = tid & 31;
    int w    = tid >> 5;        // warp 0..15
    int g    = lane >> 2;       // 0..7
    int tg   = lane & 3;        // 0..3
    int bh   = blockIdx.y;
    int q0   = blockIdx.x * 16;

    const __nv_bfloat16* Kbh = Kh  + (size_t)bh * SS * DHH;
    const __nv_bfloat16* Kbl = Kl  + (size_t)bh * SS * DHH;
    const __nv_bfloat16* Vbh = Vth + (size_t)bh * DHH * SS;
    const __nv_bfloat16* Vbl = Vtl + (size_t)bh * DHH * SS;

    char* kwbase = sm + w * KW_STRIDE;
    char* vwbase = sm + VBASE + w * VW_STRIDE;
    const int kb0 = w * 8;       // this warp's key offset within each 128-tile

    auto prefetchK = [&](int t) {
        char* buf = kwbase + (t & 1) * KBUF;
        int kb = t * 128 + kb0;
        #pragma unroll
        for (int i = 0; i < 4; ++i) {
            int idx  = lane + i * 32;          // 0..127
            int part = idx >> 6;               // 0 hi, 1 lo
            int r    = (idx >> 3) & 7;
            int c8   = idx & 7;
            const __nv_bfloat16* src = (part ? Kbl : Kbh)
                + (size_t)(kb + r) * DHH + c8 * 8;
            cpasync16(buf + part * KPART + r * 144 + c8 * 16, src);
        }
        cp_commit();
    };
    auto prefetchV = [&](int t) {
        char* buf = vwbase + (t & 1) * VBUF;
        int kb = t * 128 + kb0;
        #pragma unroll
        for (int i = 0; i < 4; ++i) {
            int idx  = lane + i * 32;          // 0..127
            int part = idx >> 6;
            int d    = idx & 63;
            const __nv_bfloat16* src = (part ? Vbl : Vbh) + (size_t)d * SS + kb;
            cpasync16(buf + part * VPART + d * 16, src);
        }
        cp_commit();
    };

    prefetchK(0);
    prefetchK(1);

    // Stage Q (16 x 64 hi + lo) into smem, 144B pitch.
    {
        const unsigned* Qh32 = (const unsigned*)(Qh + (size_t)(bh * SS + q0) * DHH);
        const unsigned* Ql32 = (const unsigned*)(Ql + (size_t)(bh * SS + q0) * DHH);
        int row = tid >> 5;
        int c2  = tid & 31;
        *(unsigned*)(sm + QBASE + row * 144 + c2 * 4) = Qh32[row * 32 + c2];
        *(unsigned*)(sm + QLOB  + row * 144 + c2 * 4) = Ql32[row * 32 + c2];
    }
    __syncthreads();   // sync #1: Q visible to all warps

    const float scale = 0.125f;   // 1/sqrt(64)
    int li = lane & 7, lm = lane >> 3;
    unsigned qoff = (unsigned)((li + (lm & 1) * 8) * 144 + (lm >> 1) * 16);

    float P[64];
    int2 mA = *(const int2*)&mask[(size_t)(q0 + g) * SS + kb0 + 2 * tg];
    int2 mB = *(const int2*)&mask[(size_t)(q0 + g + 8) * SS + kb0 + 2 * tg];

    // ---- Phase 1: scores (no syncthreads; per-warp pipeline) ----
    #pragma unroll
    for (int t = 0; t < 16; ++t) {
        if (t < 15) cp_wait<1>(); else cp_wait<0>();
        const char* kbuf = kwbase + (t & 1) * KBUF;

        float cHH[4] = {0,0,0,0}, cHL[4] = {0,0,0,0}, cLH[4] = {0,0,0,0};
        #pragma unroll
        for (int ks = 0; ks < 4; ++ks) {
            unsigned ah[4], al[4];
            ldmx4(ah[0], ah[1], ah[2], ah[3], sm + QBASE + qoff + ks * 32);
            ldmx4(al[0], al[1], al[2], al[3], sm + QLOB + qoff + ks * 32);
            unsigned bhv[2], blv[2];
            bhv[0] = *(const unsigned*)(kbuf + g * 144 + (ks * 16 + 2 * tg) * 2);
            bhv[1] = *(const unsigned*)(kbuf + g * 144 + (ks * 16 + 2 * tg + 8) * 2);
            blv[0] = *(const unsigned*)(kbuf + KPART + g * 144 + (ks * 16 + 2 * tg) * 2);
            blv[1] = *(const unsigned*)(kbuf + KPART + g * 144 + (ks * 16 + 2 * tg + 8) * 2);
            mma_bf16(cHH, ah, bhv);
            mma_bf16(cHL, ah, blv);
            mma_bf16(cLH, al, bhv);
        }
        if (t + 2 < 16) prefetchK(t + 2);

        P[4*t+0] = mA.x ? (cHH[0] + cHL[0] + cLH[0]) * scale : -1e34f;
        P[4*t+1] = mA.y ? (cHH[1] + cHL[1] + cLH[1]) * scale : -1e34f;
        P[4*t+2] = mB.x ? (cHH[2] + cHL[2] + cLH[2]) * scale : -1e34f;
        P[4*t+3] = mB.y ? (cHH[3] + cHL[3] + cLH[3]) * scale : -1e34f;

        if (t < 15) {
            int col = (t + 1) * 128 + kb0 + 2 * tg;
            mA = *(const int2*)&mask[(size_t)(q0 + g) * SS + col];
            mB = *(const int2*)&mask[(size_t)(q0 + g + 8) * SS + col];
        }
    }

    // ---- Phase 2: softmax over register P ----
    float mxA = -3.4e38f, mxB = -3.4e38f;
    #pragma unroll
    for (int t = 0; t < 16; ++t) {
        mxA = fmaxf(mxA, fmaxf(P[4*t+0], P[4*t+1]));
        mxB = fmaxf(mxB, fmaxf(P[4*t+2], P[4*t+3]));
    }
    mxA = fmaxf(mxA, __shfl_xor_sync(0xffffffffu, mxA, 1));
    mxA = fmaxf(mxA, __shfl_xor_sync(0xffffffffu, mxA, 2));
    mxB = fmaxf(mxB, __shfl_xor_sync(0xffffffffu, mxB, 1));
    mxB = fmaxf(mxB, __shfl_xor_sync(0xffffffffu, mxB, 2));
    if (tg == 0) {
        red[g * 16 + w]       = mxA;
        red[(g + 8) * 16 + w] = mxB;
    }
    __syncthreads();   // sync #2

    float rmA = -3.4e38f, rmB = -3.4e38f;
    #pragma unroll
    for (int i = 0; i < 16; ++i) {
        rmA = fmaxf(rmA, red[g * 16 + i]);
        rmB = fmaxf(rmB, red[(g + 8) * 16 + i]);
    }

    float sA = 0.f, sB = 0.f;
    #pragma unroll
    for (int t = 0; t < 16; ++t) {
        float e0 = __expf(P[4*t+0] - rmA);
        float e1 = __expf(P[4*t+1] - rmA);
        float e2 = __expf(P[4*t+2] - rmB);
        float e3 = __expf(P[4*t+3] - rmB);
        P[4*t+0] = e0; P[4*t+1] = e1; P[4*t+2] = e2; P[4*t+3] = e3;
        sA += e0 + e1;
        sB += e2 + e3;
    }
    sA += __shfl_xor_sync(0xffffffffu, sA, 1);
    sA += __shfl_xor_sync(0xffffffffu, sA, 2);
    sB += __shfl_xor_sync(0xffffffffu, sB, 1);
    sB += __shfl_xor_sync(0xffffffffu, sB, 2);
    if (tg == 0) {
        red[256 + g * 16 + w]       = sA;
        red[256 + (g + 8) * 16 + w] = sB;
    }
    prefetchV(0);                 // overlap V arrival with the reduce + writes
    prefetchV(1);
    __syncthreads();   // sync #3

    float smA = 0.f, smB = 0.f;
    #pragma unroll
    for (int i = 0; i < 16; ++i) {
        smA += red[256 + g * 16 + i];
        smB += red[256 + (g + 8) * 16 + i];
    }
    float invA = 1.0f / smA;
    float invB = 1.0f / smB;

    // attn output write (normalized), straight from registers
    if (write_attn) {
        float* arowA = attn_out + ((size_t)bh * SS + q0 + g) * SS + kb0 + 2 * tg;
        float* arowB = attn_out + ((size_t)bh * SS + q0 + g + 8) * SS + kb0 + 2 * tg;
        #pragma unroll
        for (int t = 0; t < 16; ++t) {
            *(float2*)(arowA + t * 128) = make_float2(P[4*t+0] * invA, P[4*t+1] * invA);
            *(float2*)(arowB + t * 128) = make_float2(P[4*t+2] * invB, P[4*t+3] * invB);
        }
    }

    // ---- Phase 3: out = P @ V via m16n8k8, per-warp keys (no syncs) ----
    float acc[8][4];
    #pragma unroll
    for (int nt = 0; nt < 8; ++nt)
        #pragma unroll
        for (int e = 0; e < 4; ++e) acc[nt][e] = 0.f;

    #pragma unroll
    for (int t = 0; t < 16; ++t) {
        if (t < 15) cp_wait<1>(); else cp_wait<0>();
        const char* vbuf = vwbase + (t & 1) * VBUF;

        unsigned pah[2], pal[2];
        split2f(make_float2(P[4*t+0] * invA, P[4*t+1] * invA), pah[0], pal[0]);
        split2f(make_float2(P[4*t+2] * invB, P[4*t+3] * invB), pah[1], pal[1]);

        #pragma unroll
        for (int nt = 0; nt < 8; ++nt) {
            unsigned bhv = *(const unsigned*)(vbuf + (nt * 8 + g) * 16 + tg * 4);
            unsigned blv = *(const unsigned*)(vbuf + VPART + (nt * 8 + g) * 16 + tg * 4);
            mma_bf16_k8(acc[nt], pah, bhv);
            mma_bf16_k8(acc[nt], pah, blv);
            mma_bf16_k8(acc[nt], pal, bhv);
        }
        if (t + 2 < 16) prefetchV(t + 2);
    }

    // per-warp partials into K region (free since phase 1; all warps past it
    // before sync #2/#3, so aliasing is safe)
    #pragma unroll
    for (int nt = 0; nt < 8; ++nt) {
        *(float2*)&partial[w * 1024 + g * 64 + nt * 8 + 2 * tg] =
            make_float2(acc[nt][0], acc[nt][1]);
        *(float2*)&partial[w * 1024 + (g + 8) * 64 + nt * 8 + 2 * tg] =
            make_float2(acc[nt][2], acc[nt][3]);
    }
    __syncthreads();   // sync #4

    // Reduce 16 warps' partials, write g_O
    {
        #pragma unroll
        for (int rep = 0; rep < 2; ++rep) {
            int o = tid + rep * 512;
            int q = o >> 6;
            int d = o & 63;
            float s = 0.f;
            #pragma unroll
            for (int ww = 0; ww < 16; ++ww)
                s += partial[ww * 1024 + o];
            O[((size_t)(bh >> 4) * SS + q0 + q) * DD + (bh & 15) * DHH + d] = s;
        }
    }
}

extern "C" void kernel_launch(void* const* d_in, const int* in_sizes, int n_in,
                              void* d_out, int out_size)
{
    const float* q    = (const float*)d_in[0];
    const float* k    = (const float*)d_in[1];
    const float* v    = (const float*)d_in[2];
    const int*   mask = (const int*)  d_in[3];
    const float* Wq   = (const float*)d_in[4];
    const float* Wk   = (const float*)d_in[5];
    const float* Wv   = (const float*)d_in[6];
    const float* Wo   = (const float*)d_in[7];
    float* out = (float*)d_out;

    __nv_bfloat16 *qh, *ql, *kh, *kl, *vth, *vtl;
    float *go;
    cudaGetSymbolAddress((void**)&qh,  g_Qh);
    cudaGetSymbolAddress((void**)&ql,  g_Ql);
    cudaGetSymbolAddress((void**)&kh,  g_Kh);
    cudaGetSymbolAddress((void**)&kl,  g_Kl);
    cudaGetSymbolAddress((void**)&vth, g_Vth);
    cudaGetSymbolAddress((void**)&vtl, g_Vtl);
    cudaGetSymbolAddress((void**)&go,  g_O);

    dim3 blkG(256);
    dim3 gridG(DD / 64, MM / 128);              // (16, 32)

    gemm_tc<0><<<gridG, blkG>>>(q, Wq, qh, ql, nullptr);
    gemm_tc<0><<<gridG, blkG>>>(k, Wk, kh, kl, nullptr);
    gemm_tc<3><<<gridG, blkG>>>(v, Wv, vth, vtl, nullptr);

    const long out_elems = (long)BB * SS * DD;  // 4194304
    int write_attn = (out_size > out_elems) ? 1 : 0;
    float* attn_out = out + out_elems;

    cudaFuncSetAttribute(attn_kernel,
                         cudaFuncAttributeMaxDynamicSharedMemorySize,
                         SMEM_ATTN);
    dim3 gridA(SS / 16, BB * HH);               // (128, 32)
    attn_kernel<<<gridA, 512, SMEM_ATTN>>>(mask, attn_out, write_attn,
                                           qh, ql, kh, kl, vth, vtl, go);

    gemm_tc<1><<<gridG, blkG>>>(go, Wo, nullptr, nullptr, out);
}

// round 14
// speedup vs baseline: 1.4743x; 1.4743x over previous
#include <cuda_runtime.h>
#include <cuda_bf16.h>
#include <cstdint>

// Problem dims (fixed)
#define BB 2
#define SS 2048
#define DD 1024
#define HH 16
#define DHH 64
#define MM (BB*SS)   // 4096

// Scratch (allocation-free rule: __device__ globals)
__device__ __nv_bfloat16 g_Qh[BB*SS*DD];
__device__ __nv_bfloat16 g_Ql[BB*SS*DD];
__device__ __nv_bfloat16 g_Kh[BB*SS*DD];
__device__ __nv_bfloat16 g_Kl[BB*SS*DD];
__device__ __nv_bfloat16 g_Vth[BB*SS*DD];   // [bh][d][key]
__device__ __nv_bfloat16 g_Vtl[BB*SS*DD];
__device__ float g_O[BB*SS*DD];

// ---------------------------------------------------------------------------
// helpers
// ---------------------------------------------------------------------------
__device__ __forceinline__ unsigned f2tf(float f) {
    unsigned u;
    asm("cvt.rna.tf32.f32 %0, %1;" : "=r"(u) : "f"(f));
    return u;
}

__device__ __forceinline__ void mma_tf32(float* c, const unsigned* a, const unsigned* b) {
    asm volatile(
        "mma.sync.aligned.m16n8k8.row.col.f32.tf32.tf32.f32 "
        "{%0,%1,%2,%3}, {%4,%5,%6,%7}, {%8,%9}, {%0,%1,%2,%3};"
        : "+f"(c[0]), "+f"(c[1]), "+f"(c[2]), "+f"(c[3])
        : "r"(a[0]), "r"(a[1]), "r"(a[2]), "r"(a[3]),
          "r"(b[0]), "r"(b[1]));
}

__device__ __forceinline__ void mma_bf16(float* c, const unsigned* a, const unsigned* b) {
    asm volatile(
        "mma.sync.aligned.m16n8k16.row.col.f32.bf16.bf16.f32 "
        "{%0,%1,%2,%3}, {%4,%5,%6,%7}, {%8,%9}, {%0,%1,%2,%3};"
        : "+f"(c[0]), "+f"(c[1]), "+f"(c[2]), "+f"(c[3])
        : "r"(a[0]), "r"(a[1]), "r"(a[2]), "r"(a[3]),
          "r"(b[0]), "r"(b[1]));
}

__device__ __forceinline__ void split2f(float2 v, unsigned& hi, unsigned& lo) {
    __nv_bfloat162 h, l;
    h.x = __float2bfloat16_rn(v.x);
    h.y = __float2bfloat16_rn(v.y);
    l.x = __float2bfloat16_rn(v.x - __bfloat162float(h.x));
    l.y = __float2bfloat16_rn(v.y - __bfloat162float(h.y));
    hi = *(unsigned*)&h;
    lo = *(unsigned*)&l;
}

__device__ __forceinline__ void cpasync16(void* dst, const void* src) {
    unsigned d = (unsigned)__cvta_generic_to_shared(dst);
    asm volatile("cp.async.cg.shared.global [%0], [%1], 16;" :: "r"(d), "l"(src));
}
__device__ __forceinline__ void cp_commit() {
    asm volatile("cp.async.commit_group;");
}
template<int N> __device__ __forceinline__ void cp_wait() {
    asm volatile("cp.async.wait_group %0;" :: "n"(N));
}

__device__ __forceinline__ void ldmx4(unsigned& r0, unsigned& r1, unsigned& r2, unsigned& r3,
                                      const void* p) {
    unsigned a = (unsigned)__cvta_generic_to_shared(p);
    asm volatile("ldmatrix.sync.aligned.m8n8.x4.shared.b16 {%0,%1,%2,%3}, [%4];"
                 : "=r"(r0), "=r"(r1), "=r"(r2), "=r"(r3) : "r"(a));
}
__device__ __forceinline__ void ldmx2(unsigned& r0, unsigned& r1, const void* p) {
    unsigned a = (unsigned)__cvta_generic_to_shared(p);
    asm volatile("ldmatrix.sync.aligned.m8n8.x2.shared.b16 {%0,%1}, [%2];"
                 : "=r"(r0), "=r"(r1) : "r"(a));
}

// ---------------------------------------------------------------------------
// Tensor-core GEMM, 3-stage cp.async pipeline: C = X @ W^T (tf32, fp32 acc).
// CTA tile 128x64, 8 warps, k-step 32, one __syncthreads per k-iteration.
// Dynamic smem: Xs[3][128][36] + Ws[3][64][36] = 82944 B -> 2 CTAs/SM.
// MODE 0: split-bf16 output, head layout [bh][s][dh]  (Q, K)
// MODE 3: split-bf16 output, transposed [bh][dh][s]   (V)
// MODE 1: fp32 row-major [M,N]                        (final)
// ---------------------------------------------------------------------------
#define GX_STRIDE 4608           // 128*36 floats per X stage
#define GW_BASE   13824          // 3 X stages
#define GW_STRIDE 2304           // 64*36 floats per W stage
#define SMEM_GEMM 82944          // (13824 + 6912) * 4

template<int MODE>
__global__ void __launch_bounds__(256, 2)
gemm_tc(const float* __restrict__ X, const float* __restrict__ W,
        __nv_bfloat16* __restrict__ Chi, __nv_bfloat16* __restrict__ Clo,
        float* __restrict__ C32)
{
    extern __shared__ float gsm[];

    int tid  = threadIdx.x;
    int lane = tid & 31;
    int wid  = tid >> 5;
    int wm = wid >> 1;
    int wn = wid & 1;
    int g  = lane >> 2;
    int tg = lane & 3;
    int row0 = blockIdx.y * 128;
    int col0 = blockIdx.x * 64;

    auto prefetch = [&](int ki) {
        int s = ki % 3;
        float* xs = gsm + s * GX_STRIDE;
        float* ws = gsm + GW_BASE + s * GW_STRIDE;
        int k0 = ki * 32;
        #pragma unroll
        for (int it = 0; it < 4; ++it) {
            int idx = tid + it * 256;
            int r  = idx >> 3;
            int c4 = (idx & 7) << 2;
            cpasync16(&xs[r * 36 + c4], &X[(size_t)(row0 + r) * DD + k0 + c4]);
        }
        #pragma unroll
        for (int it = 0; it < 2; ++it) {
            int idx = tid + it * 256;
            int r  = idx >> 3;
            int c4 = (idx & 7) << 2;
            cpasync16(&ws[r * 36 + c4], &W[(size_t)(col0 + r) * DD + k0 + c4]);
        }
        cp_commit();
    };

    prefetch(0);
    prefetch(1);

    float acc[2][4][4];
    #pragma unroll
    for (int h = 0; h < 2; ++h)
        #pragma unroll
        for (int j = 0; j < 4; ++j)
            #pragma unroll
            for (int e = 0; e < 4; ++e) acc[h][j][e] = 0.f;

    for (int ki = 0; ki < 32; ++ki) {
        if (ki < 31) cp_wait<1>(); else cp_wait<0>();
        __syncthreads();

        const float* xs = gsm + (ki % 3) * GX_STRIDE;
        const float* ws = gsm + GW_BASE + (ki % 3) * GW_STRIDE;

        if (ki + 2 < 32) prefetch(ki + 2);

        #pragma unroll
        for (int k8 = 0; k8 < 4; ++k8) {
            int kk = k8 * 8;
            unsigned a[2][4], b[4][2];
            #pragma unroll
            for (int h = 0; h < 2; ++h) {
                int r = wm * 32 + h * 16 + g;
                a[h][0] = f2tf(xs[r * 36 + kk + tg]);
                a[h][1] = f2tf(xs[(r + 8) * 36 + kk + tg]);
                a[h][2] = f2tf(xs[r * 36 + kk + tg + 4]);
                a[h][3] = f2tf(xs[(r + 8) * 36 + kk + tg + 4]);
            }
            #pragma unroll
            for (int j = 0; j < 4; ++j) {
                int n = wn * 32 + j * 8 + g;
                b[j][0] = f2tf(ws[n * 36 + kk + tg]);
                b[j][1] = f2tf(ws[n * 36 + kk + tg + 4]);
            }
            #pragma unroll
            for (int h = 0; h < 2; ++h)
                #pragma unroll
                for (int j = 0; j < 4; ++j)
                    mma_tf32(acc[h][j], a[h], b[j]);
        }
    }

    #pragma unroll
    for (int h = 0; h < 2; ++h) {
        #pragma unroll
        for (int j = 0; j < 4; ++j) {
            int m0 = row0 + wm * 32 + h * 16 + g;
            int n0 = col0 + wn * 32 + j * 8 + 2 * tg;
            #pragma unroll
            for (int half = 0; half < 2; ++half) {
                int m = m0 + half * 8;
                float vx = acc[h][j][half * 2 + 0];
                float vy = acc[h][j][half * 2 + 1];
                if (MODE == 1) {
                    float2 val; val.x = vx; val.y = vy;
                    *(float2*)&C32[(size_t)m * DD + n0] = val;
                } else if (MODE == 0) {
                    int b_ = m >> 11, s_ = m & 2047;
                    int h_ = n0 >> 6, d_ = n0 & 63;
                    size_t base = ((size_t)(((b_ << 4) + h_) * SS + s_)) * DHH + d_;
                    __nv_bfloat162 hv, lv;
                    hv.x = __float2bfloat16_rn(vx);
                    hv.y = __float2bfloat16_rn(vy);
                    lv.x = __float2bfloat16_rn(vx - __bfloat162float(hv.x));
                    lv.y = __float2bfloat16_rn(vy - __bfloat162float(hv.y));
                    *(__nv_bfloat162*)&Chi[base] = hv;
                    *(__nv_bfloat162*)&Clo[base] = lv;
                } else {           // MODE 3: transposed V
                    int b_ = m >> 11, s_ = m & 2047;
                    #pragma unroll
                    for (int e = 0; e < 2; ++e) {
                        int d = n0 + e;
                        int h_ = d >> 6, dd = d & 63;
                        size_t base = ((size_t)(((b_ << 4) + h_) * DHH + dd)) * SS + s_;
                        float v = e ? vy : vx;
                        __nv_bfloat16 hb = __float2bfloat16_rn(v);
                        Chi[base] = hb;
                        Clo[base] = __float2bfloat16_rn(v - __bfloat162float(hb));
                    }
                }
            }
        }
    }
}

// ---------------------------------------------------------------------------
// Fused attention (round-8 proven version, verbatim): cp.async double-buffered
// 128-key CTA-wide tiles, ldmatrix B-fragments, fused mask/max, slim softmax,
// 8x2 phase-3 split. CTA = 16 q rows of one (b,h), 512 threads.
// ---------------------------------------------------------------------------
#define SCS 2052
#define SMEM_ATTN 206144

__global__ void __launch_bounds__(512, 1)
attn_kernel(const int* __restrict__ mask, float* __restrict__ attn_out,
            int write_attn,
            const __nv_bfloat16* __restrict__ Qh, const __nv_bfloat16* __restrict__ Ql,
            const __nv_bfloat16* __restrict__ Kh, const __nv_bfloat16* __restrict__ Kl,
            const __nv_bfloat16* __restrict__ Vth, const __nv_bfloat16* __restrict__ Vtl,
            float* __restrict__ O)
{
    extern __shared__ float smem[];
    char* sbase = (char*)smem;
    float* sc   = smem;
    float* red  = (float*)(sbase + 205056);
    float* partial = (float*)(sbase + 131328);

    int tid  = threadIdx.x;
    int lane = tid & 31;
    int w    = tid >> 5;        // warp 0..15
    int g    = lane >> 2;       // 0..7
    int tg   = lane & 3;        // 0..3
    int bh   = blockIdx.y;
    int q0   = blockIdx.x * 16;

    const __nv_bfloat16* Kbh = Kh  + (size_t)bh * SS * DHH;
    const __nv_bfloat16* Kbl = Kl  + (size_t)bh * SS * DHH;
    const __nv_bfloat16* Vbh = Vth + (size_t)bh * DHH * SS;
    const __nv_bfloat16* Vbl = Vtl + (size_t)bh * DHH * SS;

    auto prefetchK = [&](int t) {
        char* buf = sbase + 131328 + (t & 1) * 36864;
        #pragma unroll
        for (int i = 0; i < 4; ++i) {
            int idx  = tid + i * 512;          // 0..2047
            int part = idx >> 10;              // 0 hi, 1 lo
            int r    = (idx >> 3) & 127;
            int c8   = idx & 7;
            const __nv_bfloat16* src = (part ? Kbl : Kbh)
                + ((size_t)(t * 128 + r)) * DHH + c8 * 8;
            cpasync16(buf + part * 18432 + r * 144 + c8 * 16, src);
        }
        cp_commit();
    };
    auto prefetchV = [&](int t) {
        char* buf = sbase + 131328 + (t & 1) * 34816;
        #pragma unroll
        for (int i = 0; i < 4; ++i) {
            int idx  = tid + i * 512;
            int part = idx >> 10;
            int d    = (idx >> 4) & 63;
            int c8   = idx & 15;
            const __nv_bfloat16* src = (part ? Vbl : Vbh)
                + (size_t)d * SS + t * 128 + c8 * 8;
            cpasync16(buf + part * 17408 + d * 272 + c8 * 16, src);
        }
        cp_commit();
    };

    prefetchK(0);
    prefetchK(1);

    // ---- Preload Q fragments (16 x 64, 4 k-steps), overlaps with cp.async ----
    unsigned aQh[4][4], aQl[4][4];
    {
        const __nv_bfloat16* Qbh = Qh + ((size_t)(bh * SS + q0)) * DHH;
        const __nv_bfloat16* Qbl = Ql + ((size_t)(bh * SS + q0)) * DHH;
        #pragma unroll
        for (int ks = 0; ks < 4; ++ks) {
            #pragma unroll
            for (int j = 0; j < 4; ++j) {
                int r = g + ((j & 1) ? 8 : 0);
                int c = ks * 16 + 2 * tg + ((j >= 2) ? 8 : 0);
                aQh[ks][j] = *(const unsigned*)&Qbh[(size_t)r * DHH + c];
                aQl[ks][j] = *(const unsigned*)&Qbl[(size_t)r * DHH + c];
            }
        }
    }

    const float scale = 0.125f;   // 1/sqrt(64)
    const int n0 = w * 8;         // phase-1 key group of this warp
    float mxA = -3.4e38f, mxB = -3.4e38f;

    // ---- Phase 1: scores = Q @ K^T, mask + running max fused ----
    for (int t = 0; t < 16; ++t) {
        if (t < 15) cp_wait<1>(); else cp_wait<0>();
        __syncthreads();

        const __nv_bfloat16* bKh = (const __nv_bfloat16*)(sbase + 131328 + (t & 1) * 36864);
        const __nv_bfloat16* bKl = (const __nv_bfloat16*)((char*)bKh + 18432);

        int li = lane & 7, lm = lane >> 3;
        unsigned kh[4][2], kl[4][2];
        ldmx4(kh[0][0], kh[0][1], kh[1][0], kh[1][1], bKh + (n0 + li) * 72 + lm * 8);
        ldmx4(kh[2][0], kh[2][1], kh[3][0], kh[3][1], bKh + (n0 + li) * 72 + 32 + lm * 8);
        ldmx4(kl[0][0], kl[0][1], kl[1][0], kl[1][1], bKl + (n0 + li) * 72 + lm * 8);
        ldmx4(kl[2][0], kl[2][1], kl[3][0], kl[3][1], bKl + (n0 + li) * 72 + 32 + lm * 8);

        float c[4] = {0.f, 0.f, 0.f, 0.f};
        #pragma unroll
        for (int ks = 0; ks < 4; ++ks) {
            mma_bf16(c, aQh[ks], kh[ks]);
            mma_bf16(c, aQh[ks], kl[ks]);
            mma_bf16(c, aQl[ks], kh[ks]);
        }
        __syncthreads();
        if (t + 2 < 16) prefetchK(t + 2);

        int col = t * 128 + n0 + 2 * tg;
        int2 mA = *(const int2*)&mask[(size_t)(q0 + g) * SS + col];
        int2 mB = *(const int2*)&mask[(size_t)(q0 + g + 8) * SS + col];
        float s0 = mA.x ? c[0] * scale : -1e34f;
        float s1 = mA.y ? c[1] * scale : -1e34f;
        float s2 = mB.x ? c[2] * scale : -1e34f;
        float s3 = mB.y ? c[3] * scale : -1e34f;
        mxA = fmaxf(mxA, fmaxf(s0, s1));
        mxB = fmaxf(mxB, fmaxf(s2, s3));
        *(float2*)&sc[g * SCS + col]       = make_float2(s0, s1);
        *(float2*)&sc[(g + 8) * SCS + col] = make_float2(s2, s3);
    }

    // quad-reduce max, store per-warp row maxes
    mxA = fmaxf(mxA, __shfl_xor_sync(0xffffffffu, mxA, 1));
    mxA = fmaxf(mxA, __shfl_xor_sync(0xffffffffu, mxA, 2));
    mxB = fmaxf(mxB, __shfl_xor_sync(0xffffffffu, mxB, 1));
    mxB = fmaxf(mxB, __shfl_xor_sync(0xffffffffu, mxB, 2));
    if (tg == 0) {
        red[g * 16 + w]       = mxA;
        red[(g + 8) * 16 + w] = mxB;
    }
    __syncthreads();

    // ---- prefetch V tiles 0,1 (overlaps softmax) ----
    prefetchV(0);
    prefetchV(1);

    // ---- Phase 2: softmax row w (one warp per row) ----
    {
        float mx = red[w * 16 + (lane & 15)];
        #pragma unroll
        for (int o = 8; o; o >>= 1)
            mx = fmaxf(mx, __shfl_xor_sync(0xffffffffu, mx, o));

        float* srow = sc + w * SCS;
        float sum = 0.f;
        #pragma unroll 4
        for (int j = lane * 4; j < SS; j += 128) {
            float4 sv = *(float4*)&srow[j];
            sv.x = __expf(sv.x - mx);
            sv.y = __expf(sv.y - mx);
            sv.z = __expf(sv.z - mx);
            sv.w = __expf(sv.w - mx);
            *(float4*)&srow[j] = sv;
            sum += sv.x + sv.y + sv.z + sv.w;
        }
        #pragma unroll
        for (int o = 16; o; o >>= 1)
            sum += __shfl_xor_sync(0xffffffffu, sum, o);
        float inv = 1.0f / sum;
        if (lane == 0) red[256 + w] = inv;
        __syncthreads();

        // normalized attn write (STG.128), sc keeps unnormalized exp
        if (write_attn) {
            float* arow = attn_out + ((size_t)bh * SS + q0 + w) * SS;
            #pragma unroll 4
            for (int j = lane * 4; j < SS; j += 128) {
                float4 sv = *(float4*)&srow[j];
                sv.x *= inv; sv.y *= inv; sv.z *= inv; sv.w *= inv;
                *(float4*)&arow[j] = sv;
            }
        }
    }

    float invA = red[256 + g];
    float invB = red[256 + g + 8];

    // ---- Phase 3: out = P @ V.  8-way key split x 2-way d split. ----
    {
        int kg  = w >> 1;             // key subgroup 0..7 (16 keys each)
        int dh2 = (w & 1) * 32;       // d half

        float acc[4][4];
        #pragma unroll
        for (int i = 0; i < 4; ++i)
            #pragma unroll
            for (int e = 0; e < 4; ++e) acc[i][e] = 0.f;

        int li = lane & 7, lm = (lane >> 3) & 1;

        for (int t = 0; t < 16; ++t) {
            if (t < 15) cp_wait<1>(); else cp_wait<0>();
            __syncthreads();

            const __nv_bfloat16* bVh = (const __nv_bfloat16*)(sbase + 131328 + (t & 1) * 34816);
            const __nv_bfloat16* bVl = (const __nv_bfloat16*)((char*)bVh + 17408);

            // A fragment: P rows g,g+8, keys t*128 + kg*16 + {2tg, 2tg+8}
            int kk = t * 128 + kg * 16;
            unsigned pa_h[4], pa_l[4];
            {
                float2 p0 = *(float2*)&sc[g * SCS + kk + 2 * tg];
                float2 p1 = *(float2*)&sc[(g + 8) * SCS + kk + 2 * tg];
                float2 p2 = *(float2*)&sc[g * SCS + kk + 2 * tg + 8];
                float2 p3 = *(float2*)&sc[(g + 8) * SCS + kk + 2 * tg + 8];
                p0.x *= invA; p0.y *= invA; p2.x *= invA; p2.y *= invA;
                p1.x *= invB; p1.y *= invB; p3.x *= invB; p3.y *= invB;
                split2f(p0, pa_h[0], pa_l[0]);
                split2f(p1, pa_h[1], pa_l[1]);
                split2f(p2, pa_h[2], pa_l[2]);
                split2f(p3, pa_h[3], pa_l[3]);
            }

            int kin = kg * 16;
            #pragma unroll
            for (int nt = 0; nt < 4; ++nt) {
                int nd = dh2 + nt * 8;
                unsigned bh0[2], bl0[2];
                ldmx2(bh0[0], bh0[1], bVh + (nd + li) * 136 + kin + lm * 8);
                ldmx2(bl0[0], bl0[1], bVl + (nd + li) * 136 + kin + lm * 8);
                mma_bf16(acc[nt], pa_h, bh0);
                mma_bf16(acc[nt], pa_h, bl0);
                mma_bf16(acc[nt], pa_l, bh0);
            }
            __syncthreads();
            if (t + 2 < 16) prefetchV(t + 2);
        }
        __syncthreads();

        // partial[kg][q][d]
        #pragma unroll
        for (int nt = 0; nt < 4; ++nt) {
            int nd = dh2 + nt * 8 + 2 * tg;
            *(float2*)&partial[kg * 1024 + g * 64 + nd] =
                make_float2(acc[nt][0], acc[nt][1]);
            *(float2*)&partial[kg * 1024 + (g + 8) * 64 + nd] =
                make_float2(acc[nt][2], acc[nt][3]);
        }
    }
    __syncthreads();

    // ---- Reduce 8 key-subgroups, write g_O ----
    {
        int b_ = bh >> 4;
        int h_ = bh & 15;
        #pragma unroll
        for (int rep = 0; rep < 2; ++rep) {
            int o = tid + rep * 512;
            int q = o >> 6;
            int d = o & 63;
            float s = 0.f;
            #pragma unroll
            for (int kg = 0; kg < 8; ++kg)
                s += partial[kg * 1024 + o];
            O[((size_t)(b_ * SS + q0 + q)) * DD + h_ * DHH + d] = s;
        }
    }
}

extern "C" void kernel_launch(void* const* d_in, const int* in_sizes, int n_in,
                              void* d_out, int out_size)
{
    const float* q    = (const float*)d_in[0];
    const float* k    = (const float*)d_in[1];
    const float* v    = (const float*)d_in[2];
    const int*   mask = (const int*)  d_in[3];
    const float* Wq   = (const float*)d_in[4];
    const float* Wk   = (const float*)d_in[5];
    const float* Wv   = (const float*)d_in[6];
    const float* Wo   = (const float*)d_in[7];
    float* out = (float*)d_out;

    __nv_bfloat16 *qh, *ql, *kh, *kl, *vth, *vtl;
    float *go;
    cudaGetSymbolAddress((void**)&qh,  g_Qh);
    cudaGetSymbolAddress((void**)&ql,  g_Ql);
    cudaGetSymbolAddress((void**)&kh,  g_Kh);
    cudaGetSymbolAddress((void**)&kl,  g_Kl);
    cudaGetSymbolAddress((void**)&vth, g_Vth);
    cudaGetSymbolAddress((void**)&vtl, g_Vtl);
    cudaGetSymbolAddress((void**)&go,  g_O);

    cudaFuncSetAttribute(gemm_tc<0>,
                         cudaFuncAttributeMaxDynamicSharedMemorySize, SMEM_GEMM);
    cudaFuncSetAttribute(gemm_tc<3>,
                         cudaFuncAttributeMaxDynamicSharedMemorySize, SMEM_GEMM);
    cudaFuncSetAttribute(gemm_tc<1>,
                         cudaFuncAttributeMaxDynamicSharedMemorySize, SMEM_GEMM);

    dim3 blkG(256);
    dim3 gridG(DD / 64, MM / 128);              // (16, 32)

    gemm_tc<0><<<gridG, blkG, SMEM_GEMM>>>(q, Wq, qh, ql, nullptr);
    gemm_tc<0><<<gridG, blkG, SMEM_GEMM>>>(k, Wk, kh, kl, nullptr);
    gemm_tc<3><<<gridG, blkG, SMEM_GEMM>>>(v, Wv, vth, vtl, nullptr);

    const long out_elems = (long)BB * SS * DD;  // 4194304
    int write_attn = (out_size > out_elems) ? 1 : 0;
    float* attn_out = out + out_elems;

    cudaFuncSetAttribute(attn_kernel,
                         cudaFuncAttributeMaxDynamicSharedMemorySize,
                         SMEM_ATTN);
    dim3 gridA(SS / 16, BB * HH);               // (128, 32)
    attn_kernel<<<gridA, 512, SMEM_ATTN>>>(mask, attn_out, write_attn,
                                           qh, ql, kh, kl, vth, vtl, go);

    gemm_tc<1><<<gridG, blkG, SMEM_GEMM>>>(go, Wo, nullptr, nullptr, out);
}

// round 17
// speedup vs baseline: 1.6776x; 1.1379x over previous
#include <cuda_runtime.h>
#include <cuda_bf16.h>
#include <cstdint>

// Problem dims (fixed)
#define BB 2
#define SS 2048
#define DD 1024
#define HH 16
#define DHH 64
#define MM (BB*SS)   // 4096

// Scratch (allocation-free rule: __device__ globals)
__device__ __nv_bfloat16 g_Qh[BB*SS*DD];
__device__ __nv_bfloat16 g_Ql[BB*SS*DD];
__device__ __nv_bfloat16 g_Kh[BB*SS*DD];
__device__ __nv_bfloat16 g_Kl[BB*SS*DD];
__device__ __nv_bfloat16 g_Vth[BB*SS*DD];   // [bh][d][key]
__device__ __nv_bfloat16 g_Vtl[BB*SS*DD];
__device__ float g_O[BB*SS*DD];

// ---------------------------------------------------------------------------
// helpers
// ---------------------------------------------------------------------------
__device__ __forceinline__ unsigned f2tf(float f) {
    unsigned u;
    asm("cvt.rna.tf32.f32 %0, %1;" : "=r"(u) : "f"(f));
    return u;
}

__device__ __forceinline__ void mma_tf32(float* c, const unsigned* a, const unsigned* b) {
    asm volatile(
        "mma.sync.aligned.m16n8k8.row.col.f32.tf32.tf32.f32 "
        "{%0,%1,%2,%3}, {%4,%5,%6,%7}, {%8,%9}, {%0,%1,%2,%3};"
        : "+f"(c[0]), "+f"(c[1]), "+f"(c[2]), "+f"(c[3])
        : "r"(a[0]), "r"(a[1]), "r"(a[2]), "r"(a[3]),
          "r"(b[0]), "r"(b[1]));
}

__device__ __forceinline__ void mma_bf16(float* c, const unsigned* a, const unsigned* b) {
    asm volatile(
        "mma.sync.aligned.m16n8k16.row.col.f32.bf16.bf16.f32 "
        "{%0,%1,%2,%3}, {%4,%5,%6,%7}, {%8,%9}, {%0,%1,%2,%3};"
        : "+f"(c[0]), "+f"(c[1]), "+f"(c[2]), "+f"(c[3])
        : "r"(a[0]), "r"(a[1]), "r"(a[2]), "r"(a[3]),
          "r"(b[0]), "r"(b[1]));
}

__device__ __forceinline__ void split2f(float2 v, unsigned& hi, unsigned& lo) {
    __nv_bfloat162 h, l;
    h.x = __float2bfloat16_rn(v.x);
    h.y = __float2bfloat16_rn(v.y);
    l.x = __float2bfloat16_rn(v.x - __bfloat162float(h.x));
    l.y = __float2bfloat16_rn(v.y - __bfloat162float(h.y));
    hi = *(unsigned*)&h;
    lo = *(unsigned*)&l;
}

__device__ __forceinline__ void cpasync16(void* dst, const void* src) {
    unsigned d = (unsigned)__cvta_generic_to_shared(dst);
    asm volatile("cp.async.cg.shared.global [%0], [%1], 16;" :: "r"(d), "l"(src));
}
__device__ __forceinline__ void cp_commit() {
    asm volatile("cp.async.commit_group;");
}
template<int N> __device__ __forceinline__ void cp_wait() {
    asm volatile("cp.async.wait_group %0;" :: "n"(N));
}

__device__ __forceinline__ void ldmx4(unsigned& r0, unsigned& r1, unsigned& r2, unsigned& r3,
                                      const void* p) {
    unsigned a = (unsigned)__cvta_generic_to_shared(p);
    asm volatile("ldmatrix.sync.aligned.m8n8.x4.shared.b16 {%0,%1,%2,%3}, [%4];"
                 : "=r"(r0), "=r"(r1), "=r"(r2), "=r"(r3) : "r"(a));
}
__device__ __forceinline__ void ldmx2(unsigned& r0, unsigned& r1, const void* p) {
    unsigned a = (unsigned)__cvta_generic_to_shared(p);
    asm volatile("ldmatrix.sync.aligned.m8n8.x2.shared.b16 {%0,%1}, [%2];"
                 : "=r"(r0), "=r"(r1) : "r"(a));
}

// ---------------------------------------------------------------------------
// GEMM core (3-stage cp.async pipeline, tf32, 128x64 tile, 8 warps).
// Shared by the fused QKV kernel and the Wo kernel.
// ---------------------------------------------------------------------------
#define GX_STRIDE 4608           // 128*36 floats per X stage
#define GW_BASE   13824          // 3 X stages
#define GW_STRIDE 2304           // 64*36 floats per W stage
#define SMEM_GEMM 82944          // (13824 + 6912) * 4

__device__ __forceinline__ void gemm_core(
    const float* __restrict__ X, const float* __restrict__ W,
    float* gsm, int row0, int col0, int tid,
    float acc[2][4][4])
{
    int lane = tid & 31;
    int wid  = tid >> 5;
    int wm = wid >> 1;
    int wn = wid & 1;
    int g  = lane >> 2;
    int tg = lane & 3;

    auto prefetch = [&](int ki) {
        int s = ki % 3;
        float* xs = gsm + s * GX_STRIDE;
        float* ws = gsm + GW_BASE + s * GW_STRIDE;
        int k0 = ki * 32;
        #pragma unroll
        for (int it = 0; it < 4; ++it) {
            int idx = tid + it * 256;
            int r  = idx >> 3;
            int c4 = (idx & 7) << 2;
            cpasync16(&xs[r * 36 + c4], &X[(size_t)(row0 + r) * DD + k0 + c4]);
        }
        #pragma unroll
        for (int it = 0; it < 2; ++it) {
            int idx = tid + it * 256;
            int r  = idx >> 3;
            int c4 = (idx & 7) << 2;
            cpasync16(&ws[r * 36 + c4], &W[(size_t)(col0 + r) * DD + k0 + c4]);
        }
        cp_commit();
    };

    prefetch(0);
    prefetch(1);

    #pragma unroll
    for (int h = 0; h < 2; ++h)
        #pragma unroll
        for (int j = 0; j < 4; ++j)
            #pragma unroll
            for (int e = 0; e < 4; ++e) acc[h][j][e] = 0.f;

    for (int ki = 0; ki < 32; ++ki) {
        if (ki < 31) cp_wait<1>(); else cp_wait<0>();
        __syncthreads();

        const float* xs = gsm + (ki % 3) * GX_STRIDE;
        const float* ws = gsm + GW_BASE + (ki % 3) * GW_STRIDE;

        if (ki + 2 < 32) prefetch(ki + 2);

        #pragma unroll
        for (int k8 = 0; k8 < 4; ++k8) {
            int kk = k8 * 8;
            unsigned a[2][4], b[4][2];
            #pragma unroll
            for (int h = 0; h < 2; ++h) {
                int r = wm * 32 + h * 16 + g;
                a[h][0] = f2tf(xs[r * 36 + kk + tg]);
                a[h][1] = f2tf(xs[(r + 8) * 36 + kk + tg]);
                a[h][2] = f2tf(xs[r * 36 + kk + tg + 4]);
                a[h][3] = f2tf(xs[(r + 8) * 36 + kk + tg + 4]);
            }
            #pragma unroll
            for (int j = 0; j < 4; ++j) {
                int n = wn * 32 + j * 8 + g;
                b[j][0] = f2tf(ws[n * 36 + kk + tg]);
                b[j][1] = f2tf(ws[n * 36 + kk + tg + 4]);
            }
            #pragma unroll
            for (int h = 0; h < 2; ++h)
                #pragma unroll
                for (int j = 0; j < 4; ++j)
                    mma_tf32(acc[h][j], a[h], b[j]);
        }
    }
}

// Fused Q/K/V projection: blockIdx.z selects input/weight/output.
// z=0 -> Q (mode 0), z=1 -> K (mode 0), z=2 -> V (mode 3 transposed).
__global__ void __launch_bounds__(256, 2)
gemm_qkv(const float* __restrict__ q, const float* __restrict__ k,
         const float* __restrict__ v,
         const float* __restrict__ Wq, const float* __restrict__ Wk,
         const float* __restrict__ Wv,
         __nv_bfloat16* __restrict__ Qh, __nv_bfloat16* __restrict__ Ql,
         __nv_bfloat16* __restrict__ Kh, __nv_bfloat16* __restrict__ Kl,
         __nv_bfloat16* __restrict__ Vth, __nv_bfloat16* __restrict__ Vtl)
{
    extern __shared__ float gsm[];
    int z = blockIdx.z;
    const float* X = (z == 0) ? q  : (z == 1) ? k  : v;
    const float* W = (z == 0) ? Wq : (z == 1) ? Wk : Wv;
    __nv_bfloat16* Chi = (z == 0) ? Qh : (z == 1) ? Kh : Vth;
    __nv_bfloat16* Clo = (z == 0) ? Ql : (z == 1) ? Kl : Vtl;

    int tid  = threadIdx.x;
    int lane = tid & 31;
    int wid  = tid >> 5;
    int wm = wid >> 1, wn = wid & 1;
    int g  = lane >> 2, tg = lane & 3;
    int row0 = blockIdx.y * 128;
    int col0 = blockIdx.x * 64;

    float acc[2][4][4];
    gemm_core(X, W, gsm, row0, col0, tid, acc);

    #pragma unroll
    for (int h = 0; h < 2; ++h) {
        #pragma unroll
        for (int j = 0; j < 4; ++j) {
            int m0 = row0 + wm * 32 + h * 16 + g;
            int n0 = col0 + wn * 32 + j * 8 + 2 * tg;
            #pragma unroll
            for (int half = 0; half < 2; ++half) {
                int m = m0 + half * 8;
                float vx = acc[h][j][half * 2 + 0];
                float vy = acc[h][j][half * 2 + 1];
                int b_ = m >> 11, s_ = m & 2047;
                if (z < 2) {       // head layout [bh][s][dh]
                    int h_ = n0 >> 6, d_ = n0 & 63;
                    size_t base = ((size_t)(((b_ << 4) + h_) * SS + s_)) * DHH + d_;
                    __nv_bfloat162 hv, lv;
                    hv.x = __float2bfloat16_rn(vx);
                    hv.y = __float2bfloat16_rn(vy);
                    lv.x = __float2bfloat16_rn(vx - __bfloat162float(hv.x));
                    lv.y = __float2bfloat16_rn(vy - __bfloat162float(hv.y));
                    *(__nv_bfloat162*)&Chi[base] = hv;
                    *(__nv_bfloat162*)&Clo[base] = lv;
                } else {           // V transposed [bh][dh][s]
                    #pragma unroll
                    for (int e = 0; e < 2; ++e) {
                        int d = n0 + e;
                        int h_ = d >> 6, dd = d & 63;
                        size_t base = ((size_t)(((b_ << 4) + h_) * DHH + dd)) * SS + s_;
                        float val = e ? vy : vx;
                        __nv_bfloat16 hb = __float2bfloat16_rn(val);
                        Chi[base] = hb;
                        Clo[base] = __float2bfloat16_rn(val - __bfloat162float(hb));
                    }
                }
            }
        }
    }
}

// Wo GEMM: fp32 row-major output.
__global__ void __launch_bounds__(256, 2)
gemm_wo(const float* __restrict__ X, const float* __restrict__ W,
        float* __restrict__ C32)
{
    extern __shared__ float gsm[];
    int tid  = threadIdx.x;
    int lane = tid & 31;
    int wid  = tid >> 5;
    int wm = wid >> 1, wn = wid & 1;
    int g  = lane >> 2, tg = lane & 3;
    int row0 = blockIdx.y * 128;
    int col0 = blockIdx.x * 64;

    float acc[2][4][4];
    gemm_core(X, W, gsm, row0, col0, tid, acc);

    #pragma unroll
    for (int h = 0; h < 2; ++h)
        #pragma unroll
        for (int j = 0; j < 4; ++j) {
            int m0 = row0 + wm * 32 + h * 16 + g;
            int n0 = col0 + wn * 32 + j * 8 + 2 * tg;
            #pragma unroll
            for (int half = 0; half < 2; ++half) {
                int m = m0 + half * 8;
                float2 val;
                val.x = acc[h][j][half * 2 + 0];
                val.y = acc[h][j][half * 2 + 1];
                *(float2*)&C32[(size_t)m * DD + n0] = val;
            }
        }
}

// ---------------------------------------------------------------------------
// Fused attention: round-8 structure + phase-1 ILP (3 accumulator chains) +
// mask register prefetch. CTA = 16 q rows of one (b,h), 512 threads.
// ---------------------------------------------------------------------------
#define SCS 2052
#define SMEM_ATTN 206144

__global__ void __launch_bounds__(512, 1)
attn_kernel(const int* __restrict__ mask, float* __restrict__ attn_out,
            int write_attn,
            const __nv_bfloat16* __restrict__ Qh, const __nv_bfloat16* __restrict__ Ql,
            const __nv_bfloat16* __restrict__ Kh, const __nv_bfloat16* __restrict__ Kl,
            const __nv_bfloat16* __restrict__ Vth, const __nv_bfloat16* __restrict__ Vtl,
            float* __restrict__ O)
{
    extern __shared__ float smem[];
    char* sbase = (char*)smem;
    float* sc   = smem;
    float* red  = (float*)(sbase + 205056);
    float* partial = (float*)(sbase + 131328);

    int tid  = threadIdx.x;
    int lane = tid & 31;
    int w    = tid >> 5;        // warp 0..15
    int g    = lane >> 2;       // 0..7
    int tg   = lane & 3;        // 0..3
    int bh   = blockIdx.y;
    int q0   = blockIdx.x * 16;

    const __nv_bfloat16* Kbh = Kh  + (size_t)bh * SS * DHH;
    const __nv_bfloat16* Kbl = Kl  + (size_t)bh * SS * DHH;
    const __nv_bfloat16* Vbh = Vth + (size_t)bh * DHH * SS;
    const __nv_bfloat16* Vbl = Vtl + (size_t)bh * DHH * SS;

    auto prefetchK = [&](int t) {
        char* buf = sbase + 131328 + (t & 1) * 36864;
        #pragma unroll
        for (int i = 0; i < 4; ++i) {
            int idx  = tid + i * 512;          // 0..2047
            int part = idx >> 10;              // 0 hi, 1 lo
            int r    = (idx >> 3) & 127;
            int c8   = idx & 7;
            const __nv_bfloat16* src = (part ? Kbl : Kbh)
                + ((size_t)(t * 128 + r)) * DHH + c8 * 8;
            cpasync16(buf + part * 18432 + r * 144 + c8 * 16, src);
        }
        cp_commit();
    };
    auto prefetchV = [&](int t) {
        char* buf = sbase + 131328 + (t & 1) * 34816;
        #pragma unroll
        for (int i = 0; i < 4; ++i) {
            int idx  = tid + i * 512;
            int part = idx >> 10;
            int d    = (idx >> 4) & 63;
            int c8   = idx & 15;
            const __nv_bfloat16* src = (part ? Vbl : Vbh)
                + (size_t)d * SS + t * 128 + c8 * 8;
            cpasync16(buf + part * 17408 + d * 272 + c8 * 16, src);
        }
        cp_commit();
    };

    prefetchK(0);
    prefetchK(1);

    // ---- Preload Q fragments (16 x 64, 4 k-steps), overlaps with cp.async ----
    unsigned aQh[4][4], aQl[4][4];
    {
        const __nv_bfloat16* Qbh = Qh + ((size_t)(bh * SS + q0)) * DHH;
        const __nv_bfloat16* Qbl = Ql + ((size_t)(bh * SS + q0)) * DHH;
        #pragma unroll
        for (int ks = 0; ks < 4; ++ks) {
            #pragma unroll
            for (int j = 0; j < 4; ++j) {
                int r = g + ((j & 1) ? 8 : 0);
                int c = ks * 16 + 2 * tg + ((j >= 2) ? 8 : 0);
                aQh[ks][j] = *(const unsigned*)&Qbh[(size_t)r * DHH + c];
                aQl[ks][j] = *(const unsigned*)&Qbl[(size_t)r * DHH + c];
            }
        }
    }

    const float scale = 0.125f;   // 1/sqrt(64)
    const int n0 = w * 8;         // phase-1 key group of this warp
    float mxA = -3.4e38f, mxB = -3.4e38f;

    // mask register prefetch for tile 0
    int2 mA = *(const int2*)&mask[(size_t)(q0 + g) * SS + n0 + 2 * tg];
    int2 mB = *(const int2*)&mask[(size_t)(q0 + g + 8) * SS + n0 + 2 * tg];

    // ---- Phase 1: scores = Q @ K^T, mask + running max fused ----
    for (int t = 0; t < 16; ++t) {
        if (t < 15) cp_wait<1>(); else cp_wait<0>();
        __syncthreads();

        const __nv_bfloat16* bKh = (const __nv_bfloat16*)(sbase + 131328 + (t & 1) * 36864);
        const __nv_bfloat16* bKl = (const __nv_bfloat16*)((char*)bKh + 18432);

        int li = lane & 7, lm = lane >> 3;
        unsigned kh[4][2], kl[4][2];
        ldmx4(kh[0][0], kh[0][1], kh[1][0], kh[1][1], bKh + (n0 + li) * 72 + lm * 8);
        ldmx4(kh[2][0], kh[2][1], kh[3][0], kh[3][1], bKh + (n0 + li) * 72 + 32 + lm * 8);
        ldmx4(kl[0][0], kl[0][1], kl[1][0], kl[1][1], bKl + (n0 + li) * 72 + lm * 8);
        ldmx4(kl[2][0], kl[2][1], kl[3][0], kl[3][1], bKl + (n0 + li) * 72 + 32 + lm * 8);

        // 3 independent accumulator chains (ILP on the tensor pipe)
        float cHH[4] = {0.f, 0.f, 0.f, 0.f};
        float cHL[4] = {0.f, 0.f, 0.f, 0.f};
        float cLH[4] = {0.f, 0.f, 0.f, 0.f};
        #pragma unroll
        for (int ks = 0; ks < 4; ++ks) {
            mma_bf16(cHH, aQh[ks], kh[ks]);
            mma_bf16(cHL, aQh[ks], kl[ks]);
            mma_bf16(cLH, aQl[ks], kh[ks]);
        }
        __syncthreads();
        if (t + 2 < 16) prefetchK(t + 2);

        int col = t * 128 + n0 + 2 * tg;
        float s0 = mA.x ? (cHH[0] + cHL[0] + cLH[0]) * scale : -1e34f;
        float s1 = mA.y ? (cHH[1] + cHL[1] + cLH[1]) * scale : -1e34f;
        float s2 = mB.x ? (cHH[2] + cHL[2] + cLH[2]) * scale : -1e34f;
        float s3 = mB.y ? (cHH[3] + cHL[3] + cLH[3]) * scale : -1e34f;
        mxA = fmaxf(mxA, fmaxf(s0, s1));
        mxB = fmaxf(mxB, fmaxf(s2, s3));
        *(float2*)&sc[g * SCS + col]       = make_float2(s0, s1);
        *(float2*)&sc[(g + 8) * SCS + col] = make_float2(s2, s3);

        // prefetch next tile's mask into registers (hidden by next wait+MMAs)
        if (t < 15) {
            int ncol = (t + 1) * 128 + n0 + 2 * tg;
            mA = *(const int2*)&mask[(size_t)(q0 + g) * SS + ncol];
            mB = *(const int2*)&mask[(size_t)(q0 + g + 8) * SS + ncol];
        }
    }

    // quad-reduce max, store per-warp row maxes
    mxA = fmaxf(mxA, __shfl_xor_sync(0xffffffffu, mxA, 1));
    mxA = fmaxf(mxA, __shfl_xor_sync(0xffffffffu, mxA, 2));
    mxB = fmaxf(mxB, __shfl_xor_sync(0xffffffffu, mxB, 1));
    mxB = fmaxf(mxB, __shfl_xor_sync(0xffffffffu, mxB, 2));
    if (tg == 0) {
        red[g * 16 + w]       = mxA;
        red[(g + 8) * 16 + w] = mxB;
    }
    __syncthreads();

    // ---- prefetch V tiles 0,1 (overlaps softmax) ----
    prefetchV(0);
    prefetchV(1);

    // ---- Phase 2: softmax row w (one warp per row) ----
    {
        float mx = red[w * 16 + (lane & 15)];
        #pragma unroll
        for (int o = 8; o; o >>= 1)
            mx = fmaxf(mx, __shfl_xor_sync(0xffffffffu, mx, o));

        float* srow = sc + w * SCS;
        float sum = 0.f;
        #pragma unroll 4
        for (int j = lane * 4; j < SS; j += 128) {
            float4 sv = *(float4*)&srow[j];
            sv.x = __expf(sv.x - mx);
            sv.y = __expf(sv.y - mx);
            sv.z = __expf(sv.z - mx);
            sv.w = __expf(sv.w - mx);
            *(float4*)&srow[j] = sv;
            sum += sv.x + sv.y + sv.z + sv.w;
        }
        #pragma unroll
        for (int o = 16; o; o >>= 1)
            sum += __shfl_xor_sync(0xffffffffu, sum, o);
        float inv = 1.0f / sum;
        if (lane == 0) red[256 + w] = inv;
        __syncthreads();

        // normalized attn write (STG.128), sc keeps unnormalized exp
        if (write_attn) {
            float* arow = attn_out + ((size_t)bh * SS + q0 + w) * SS;
            #pragma unroll 4
            for (int j = lane * 4; j < SS; j += 128) {
                float4 sv = *(float4*)&srow[j];
                sv.x *= inv; sv.y *= inv; sv.z *= inv; sv.w *= inv;
                *(float4*)&arow[j] = sv;
            }
        }
    }

    float invA = red[256 + g];
    float invB = red[256 + g + 8];

    // ---- Phase 3: out = P @ V.  8-way key split x 2-way d split. ----
    {
        int kg  = w >> 1;             // key subgroup 0..7 (16 keys each)
        int dh2 = (w & 1) * 32;       // d half

        float acc[4][4];
        #pragma unroll
        for (int i = 0; i < 4; ++i)
            #pragma unroll
            for (int e = 0; e < 4; ++e) acc[i][e] = 0.f;

        int li = lane & 7, lm = (lane >> 3) & 1;

        for (int t = 0; t < 16; ++t) {
            if (t < 15) cp_wait<1>(); else cp_wait<0>();
            __syncthreads();

            const __nv_bfloat16* bVh = (const __nv_bfloat16*)(sbase + 131328 + (t & 1) * 34816);
            const __nv_bfloat16* bVl = (const __nv_bfloat16*)((char*)bVh + 17408);

            // A fragment: P rows g,g+8, keys t*128 + kg*16 + {2tg, 2tg+8}
            int kk = t * 128 + kg * 16;
            unsigned pa_h[4], pa_l[4];
            {
                float2 p0 = *(float2*)&sc[g * SCS + kk + 2 * tg];
                float2 p1 = *(float2*)&sc[(g + 8) * SCS + kk + 2 * tg];
                float2 p2 = *(float2*)&sc[g * SCS + kk + 2 * tg + 8];
                float2 p3 = *(float2*)&sc[(g + 8) * SCS + kk + 2 * tg + 8];
                p0.x *= invA; p0.y *= invA; p2.x *= invA; p2.y *= invA;
                p1.x *= invB; p1.y *= invB; p3.x *= invB; p3.y *= invB;
                split2f(p0, pa_h[0], pa_l[0]);
                split2f(p1, pa_h[1], pa_l[1]);
                split2f(p2, pa_h[2], pa_l[2]);
                split2f(p3, pa_h[3], pa_l[3]);
            }

            int kin = kg * 16;
            #pragma unroll
            for (int nt = 0; nt < 4; ++nt) {
                int nd = dh2 + nt * 8;
                unsigned bh0[2], bl0[2];
                ldmx2(bh0[0], bh0[1], bVh + (nd + li) * 136 + kin + lm * 8);
                ldmx2(bl0[0], bl0[1], bVl + (nd + li) * 136 + kin + lm * 8);
                mma_bf16(acc[nt], pa_h, bh0);
                mma_bf16(acc[nt], pa_h, bl0);
                mma_bf16(acc[nt], pa_l, bh0);
            }
            __syncthreads();
            if (t + 2 < 16) prefetchV(t + 2);
        }
        __syncthreads();

        // partial[kg][q][d]
        #pragma unroll
        for (int nt = 0; nt < 4; ++nt) {
            int nd = dh2 + nt * 8 + 2 * tg;
            *(float2*)&partial[kg * 1024 + g * 64 + nd] =
                make_float2(acc[nt][0], acc[nt][1]);
            *(float2*)&partial[kg * 1024 + (g + 8) * 64 + nd] =
                make_float2(acc[nt][2], acc[nt][3]);
        }
    }
    __syncthreads();

    // ---- Reduce 8 key-subgroups, write g_O ----
    {
        int b_ = bh >> 4;
        int h_ = bh & 15;
        #pragma unroll
        for (int rep = 0; rep < 2; ++rep) {
            int o = tid + rep * 512;
            int q = o >> 6;
            int d = o & 63;
            float s = 0.f;
            #pragma unroll
            for (int kg = 0; kg < 8; ++kg)
                s += partial[kg * 1024 + o];
            O[((size_t)(b_ * SS + q0 + q)) * DD + h_ * DHH + d] = s;
        }
    }
}

extern "C" void kernel_launch(void* const* d_in, const int* in_sizes, int n_in,
                              void* d_out, int out_size)
{
    const float* q    = (const float*)d_in[0];
    const float* k    = (const float*)d_in[1];
    const float* v    = (const float*)d_in[2];
    const int*   mask = (const int*)  d_in[3];
    const float* Wq   = (const float*)d_in[4];
    const float* Wk   = (const float*)d_in[5];
    const float* Wv   = (const float*)d_in[6];
    const float* Wo   = (const float*)d_in[7];
    float* out = (float*)d_out;

    __nv_bfloat16 *qh, *ql, *kh, *kl, *vth, *vtl;
    float *go;
    cudaGetSymbolAddress((void**)&qh,  g_Qh);
    cudaGetSymbolAddress((void**)&ql,  g_Ql);
    cudaGetSymbolAddress((void**)&kh,  g_Kh);
    cudaGetSymbolAddress((void**)&kl,  g_Kl);
    cudaGetSymbolAddress((void**)&vth, g_Vth);
    cudaGetSymbolAddress((void**)&vtl, g_Vtl);
    cudaGetSymbolAddress((void**)&go,  g_O);

    cudaFuncSetAttribute(gemm_qkv,
                         cudaFuncAttributeMaxDynamicSharedMemorySize, SMEM_GEMM);
    cudaFuncSetAttribute(gemm_wo,
                         cudaFuncAttributeMaxDynamicSharedMemorySize, SMEM_GEMM);

    dim3 blkG(256);
    dim3 gridQKV(DD / 64, MM / 128, 3);         // (16, 32, 3)
    gemm_qkv<<<gridQKV, blkG, SMEM_GEMM>>>(q, k, v, Wq, Wk, Wv,
                                           qh, ql, kh, kl, vth, vtl);

    const long out_elems = (long)BB * SS * DD;  // 4194304
    int write_attn = (out_size > out_elems) ? 1 : 0;
    float* attn_out = out + out_elems;

    cudaFuncSetAttribute(attn_kernel,
                         cudaFuncAttributeMaxDynamicSharedMemorySize,
                         SMEM_ATTN);
    dim3 gridA(SS / 16, BB * HH);               // (128, 32)
    attn_kernel<<<gridA, 512, SMEM_ATTN>>>(mask, attn_out, write_attn,
                                           qh, ql, kh, kl, vth, vtl, go);

    dim3 gridW(DD / 64, MM / 128);              // (16, 32)
    gemm_wo<<<gridW, blkG, SMEM_GEMM>>>(go, Wo, out);
}